// round 7
// baseline (speedup 1.0000x reference)
#include <cuda_runtime.h>
#include <cstdint>

typedef unsigned long long u64;
typedef unsigned int u32;

#define NBATCH 8
#define NLVL 5
#define NBL 40
#define NCH 16
#define NPAD 1024
#define CAND 4096
#define IMGSZ 800.0f
#define CLIPV 4.135166556742356f

__constant__ int c_h[NLVL]   = {200, 100, 50, 25, 13};
__constant__ int c_n[NLVL]   = {120000, 30000, 7500, 1875, 507};
__constant__ int c_off[NLVL] = {0, 120000, 150000, 157500, 159375};
__constant__ int c_k[NLVL]   = {1000, 1000, 1000, 1000, 507};

__device__ u32    g_hist16[NBL][NCH][4096];
__device__ u32    g_B[NBL];
__device__ int    g_ccnt[NBL];
__device__ int    g_arrive[NBL];      // zero-init; reset by consumer
__device__ int    g_done[NBATCH];     // zero-init; reset by consumer
__device__ u64    g_cand[NBL][CAND];
__device__ float4 g_kb  [NBL][NPAD];
__device__ u32    g_kkey[NBL][NPAD];
__device__ int    g_kcnt[NBL];

__device__ __forceinline__ u32 fkey(float f) {
    u32 u = __float_as_uint(f);
    return u ^ ((u32)((int)u >> 31) | 0x80000000u);
}
__device__ __forceinline__ float unfkey(u32 enc) {
    u32 u = (enc & 0x80000000u) ? (enc ^ 0x80000000u) : ~enc;
    return __uint_as_float(u);
}

__device__ __forceinline__ int bscan(int v, int* ws, int tid, int* total) {
    int lane = tid & 31, wid = tid >> 5;
    int x = v;
#pragma unroll
    for (int o = 1; o < 32; o <<= 1) {
        int y = __shfl_up_sync(~0u, x, o);
        if (lane >= o) x += y;
    }
    if (lane == 31) ws[wid] = x;
    __syncthreads();
    if (wid == 0) {
        int y = ws[lane];
#pragma unroll
        for (int o = 1; o < 32; o <<= 1) {
            int z = __shfl_up_sync(~0u, y, o);
            if (lane >= o) y += z;
        }
        ws[lane] = y;
    }
    __syncthreads();
    int base = wid ? ws[wid - 1] : 0;
    int tot = ws[31];
    __syncthreads();
    *total = tot;
    return base + x - v;
}

__device__ __forceinline__ void bitonic_desc(u64* a, int n, int tid) {
    for (int sz = 2; sz <= n; sz <<= 1)
        for (int st = sz >> 1; st >= 1; st >>= 1) {
            __syncthreads();
            for (int t = tid; t < (n >> 1); t += 1024) {
                int i = t + (t & ~(st - 1));
                int j = i + st;
                u64 x = a[i], y = a[j];
                if (((i & sz) == 0) ? (x < y) : (x > y)) { a[i] = y; a[j] = x; }
            }
        }
    __syncthreads();
}

// ---- K0: chunk histograms; last-arriving chunk block picks threshold ------
__global__ void k_histthresh(const float* __restrict__ o0, const float* __restrict__ o1,
                             const float* __restrict__ o2, const float* __restrict__ o3) {
    int bl = blockIdx.x, c = blockIdx.y, tid = threadIdx.x;
    int b = bl / NLVL, l = bl % NLVL;
    if (l == 4) return;
    int h2 = c_h[l] * c_h[l], n = c_n[l];
    const float* ob = ((l == 0) ? o0 : (l == 1) ? o1 : (l == 2) ? o2 : o3) + (size_t)b * 3 * h2;
    __shared__ u32 hist[4096];
    __shared__ int misc[160];
    __shared__ int lastf;
    for (int q = tid; q < 4096; q += 256) hist[q] = 0;
    __syncthreads();
    if (l < 3) {
        const float4* ob4 = (const float4*)ob;
        int n4 = n >> 2, cs = (n4 + NCH - 1) / NCH;
        int qs = c * cs, qe = min(qs + cs, n4);
        for (int q = qs + tid; q < qe; q += 256) {
            float4 v = ob4[q];
            atomicAdd(&hist[fkey(v.x) >> 20], 1u);
            atomicAdd(&hist[fkey(v.y) >> 20], 1u);
            atomicAdd(&hist[fkey(v.z) >> 20], 1u);
            atomicAdd(&hist[fkey(v.w) >> 20], 1u);
        }
    } else {
        int cs = (n + NCH - 1) / NCH;
        int qs = c * cs, qe = min(qs + cs, n);
        for (int q = qs + tid; q < qe; q += 256)
            atomicAdd(&hist[fkey(ob[q]) >> 20], 1u);
    }
    __syncthreads();
    for (int q = tid; q < 4096; q += 256) g_hist16[bl][c][q] = hist[q];
    __threadfence();
    if (tid == 0) lastf = (atomicAdd(&g_arrive[bl], 1) == NCH - 1);
    __syncthreads();
    if (!lastf) return;
    __threadfence();
    // reduce all 16 partials and pick threshold bucket
    for (int j = tid; j < 4096; j += 256) {
        u32 s = 0;
#pragma unroll
        for (int c2 = 0; c2 < NCH; c2++) s += g_hist16[bl][c2][j];
        hist[j] = s;
    }
    __syncthreads();
    if (tid < 128) {
        u32 s = 0;
        for (int q = 0; q < 32; q++) s += hist[tid * 32 + q];
        misc[tid + 8] = (int)s;
    }
    __syncthreads();
    if (tid == 0) {
        int kk = c_k[l];
        int acc = 0, cc;
        for (cc = 127; cc > 0; cc--) {
            if (acc + misc[cc + 8] >= kk) break;
            acc += misc[cc + 8];
        }
        int bsel = cc * 32;
        for (int q = 31; q >= 0; q--) {
            int hv = (int)hist[cc * 32 + q];
            if (acc + hv >= kk) { bsel = cc * 32 + q; break; }
            acc += hv;
        }
        g_B[bl] = (u32)bsel;
        g_ccnt[bl] = 0;
        g_arrive[bl] = 0;   // ready for next replay
    }
}

// ---- K1: compact candidates >= threshold bucket ---------------------------
__global__ void k_compact(const float* __restrict__ o0, const float* __restrict__ o1,
                          const float* __restrict__ o2, const float* __restrict__ o3) {
    int bl = blockIdx.x, c = blockIdx.y, tid = threadIdx.x;
    int b = bl / NLVL, l = bl % NLVL;
    if (l == 4) return;
    int h2 = c_h[l] * c_h[l], n = c_n[l];
    const float* ob = ((l == 0) ? o0 : (l == 1) ? o1 : (l == 2) ? o2 : o3) + (size_t)b * 3 * h2;
    u32 B = g_B[bl];
    if (l < 3) {
        const float4* ob4 = (const float4*)ob;
        int n4 = n >> 2, cs = (n4 + NCH - 1) / NCH;
        int qs = c * cs, qe = min(qs + cs, n4);
        for (int q = qs + tid; q < qe; q += 256) {
            float4 v = ob4[q];
            float vv[4] = {v.x, v.y, v.z, v.w};
#pragma unroll
            for (int e4 = 0; e4 < 4; e4++) {
                u32 u = fkey(vv[e4]);
                if ((u >> 20) >= B) {
                    int pos = atomicAdd(&g_ccnt[bl], 1);
                    if (pos < CAND) {
                        int i0 = 4 * q + e4;
                        int a = (i0 >= h2) + (i0 >= 2 * h2);
                        int p = i0 - a * h2;
                        g_cand[bl][pos] = ((u64)u << 32) | (u32)(~(u32)(p * 3 + a));
                    }
                }
            }
        }
    } else {
        int cs = (n + NCH - 1) / NCH;
        int qs = c * cs, qe = min(qs + cs, n);
        for (int q = qs + tid; q < qe; q += 256) {
            u32 u = fkey(ob[q]);
            if ((u >> 20) >= B) {
                int pos = atomicAdd(&g_ccnt[bl], 1);
                if (pos < CAND) {
                    int a = (q >= h2) + (q >= 2 * h2);
                    int p = q - a * h2;
                    g_cand[bl][pos] = ((u64)u << 32) | (u32)(~(u32)(p * 3 + a));
                }
            }
        }
    }
}

// ---- K2: fused sort -> decode -> mask -> NMS -> compact; last block of ----
// each batch then runs the sortless rank-merge and writes output.
// smem layout (bytes):
//   mask  [0, 131072)   u64[1024][16]   (aliased: cand u64[4096] in [0,32768),
//                                        skeys u32[5][1024] in merge phase)
//   obox  [131072, 147456) float4[1024]
//   oar   [147456, 151552) float[1024]
//   cur   [151552, 151680) u64[16]
//   nxt   [151680, 151808) u64[16]
//   misc  [151808, 152576) int[192]
#define SMEMP 152576

__global__ __launch_bounds__(1024, 1)
void k_proc(const float* __restrict__ o4,
            const float* __restrict__ dl0, const float* __restrict__ dl1,
            const float* __restrict__ dl2, const float* __restrict__ dl3,
            const float* __restrict__ dl4, const float* __restrict__ anchors,
            float4* __restrict__ out) {
    extern __shared__ unsigned char sm[];
    u64*    mask = (u64*)sm;
    u64*    cand = (u64*)sm;
    float4* obox = (float4*)(sm + 131072);
    float*  oar  = (float*)(sm + 147456);
    u64*    cur  = (u64*)(sm + 151552);
    u64*    nxt  = cur + 16;
    int*    misc = (int*)(sm + 151808);
    u32*    skeys = (u32*)sm;   // merge phase only

    int tid = threadIdx.x;
    int bl = blockIdx.x, b = bl / NLVL, l = bl % NLVL;
    int h = c_h[l], n = c_n[l], kk = c_k[l], h2 = h * h;

    // ---- phase 1: load candidates ----
    int S;
    if (l == 4) {
        const float* ob = o4 + (size_t)b * 3 * h2;
        for (int j = tid; j < NPAD; j += 1024) {
            u64 e = 0ULL;
            if (j < n) {
                int p = j / 3, a = j - p * 3, y = p / h, x = p - y * h;
                float v = ob[(a * h + y) * h + x];
                e = ((u64)fkey(v) << 32) | (u32)(~(u32)j);
            }
            cand[j] = e;
        }
        S = 1024;
    } else {
        int m = g_ccnt[bl];
        if (m > CAND) m = CAND;
        S = (m <= 1024) ? 1024 : ((m <= 2048) ? 2048 : 4096);
        for (int q = tid; q < S; q += 1024)
            cand[q] = (q < m) ? g_cand[bl][q] : 0ULL;
    }
    __syncthreads();

    // ---- phase 2: exact lax.top_k order ----
    bitonic_desc(cand, S, tid);

    // ---- phase 3: decode + clip + validity (registers) ----
    float C = 4096.0f * (float)l;
    const float* dl = (l == 0) ? dl0 : (l == 1) ? dl1 : (l == 2) ? dl2 : (l == 3) ? dl3 : dl4;
    int valid = 0;
    float cx1 = 0.f, cy1 = 0.f, cx2 = 0.f, cy2 = 0.f;
    u32 sigbits = 0;
    if (tid < kk) {
        u64 e = cand[tid];
        u32 idx = ~(u32)(e & 0xFFFFFFFFu);
        float logit = unfkey((u32)(e >> 32));
        sigbits = __float_as_uint(__fdiv_rn(1.0f, 1.0f + expf(-logit)));
        int p = (int)(idx / 3u), a = (int)idx - p * 3;
        int y = p / h, x = p - y * h;
        int gi = c_off[l] + (int)idx;
        float ax1 = anchors[4 * gi], ay1 = anchors[4 * gi + 1];
        float ax2 = anchors[4 * gi + 2], ay2 = anchors[4 * gi + 3];
        float wa = ax2 - ax1, ha = ay2 - ay1;
        float cxa = ax1 + 0.5f * wa, cya = ay1 + 0.5f * ha;
        int dbase = ((b * 12 + a * 4) * h + y) * h + x;
        float dx = dl[dbase], dy = dl[dbase + h2];
        float dw = fminf(dl[dbase + 2 * h2], CLIPV);
        float dh = fminf(dl[dbase + 3 * h2], CLIPV);
        float cx = dx * wa + cxa, cy = dy * ha + cya;
        float pw = expf(dw) * wa, ph = expf(dh) * ha;
        cx1 = fminf(fmaxf(cx - 0.5f * pw, 0.0f), IMGSZ);
        cy1 = fminf(fmaxf(cy - 0.5f * ph, 0.0f), IMGSZ);
        cx2 = fminf(fmaxf(cx + 0.5f * pw, 0.0f), IMGSZ);
        cy2 = fminf(fmaxf(cy + 0.5f * ph, 0.0f), IMGSZ);
        valid = ((cx2 - cx1) >= 1e-3f && (cy2 - cy1) >= 1e-3f) ? 1 : 0;
    }
    __syncthreads();   // all cand reads done; cand region may be reused below

    // ---- phase 4: stable compaction of valid candidates ----
    int nv;
    int vpos = bscan(valid, misc + 8, tid, &nv);
    if (valid) {
        float xo1 = cx1 + C, yo1 = cy1 + C, xo2 = cx2 + C, yo2 = cy2 + C;
        obox[vpos] = make_float4(xo1, yo1, xo2, yo2);
        oar[vpos] = (xo2 - xo1) * (yo2 - yo1);
    }
    __syncthreads();

    // ---- phase 5: IoU mask in shared (overwrites cand region) ----
    for (int t = tid; t < nv * 16; t += 1024) {
        int i = t >> 4, w = t & 15;
        u64 mword = 0;
        int j0 = w << 6;
        int jend = min(j0 + 64, nv);
        int js = max(j0, i + 1);
        if (js < jend) {
            float4 bi = obox[i];
            float ai = oar[i];
            for (int j = js; j < jend; j++) {
                float4 bj = obox[j];
                float lx = fmaxf(bi.x, bj.x), ly = fmaxf(bi.y, bj.y);
                float rx = fminf(bi.z, bj.z), ry = fminf(bi.w, bj.w);
                float ww2 = rx - lx, hh2 = ry - ly;
                if (ww2 > 0.0f && hh2 > 0.0f) {
                    float inter = ww2 * hh2;
                    float uni = ai + oar[j] - inter + 1e-9f;
                    if (__fdiv_rn(inter, uni) > 0.7f) mword |= 1ULL << (j - j0);
                }
            }
        }
        mask[(i << 4) + w] = mword;
    }
    if (tid < 16) cur[tid] = 0ULL;
    __syncthreads();

    // ---- phase 6: fixed-point greedy NMS (unique fixed point == greedy) ----
    int w = tid & 15, i0 = tid >> 4;
    for (int it = 0; it < NPAD; it++) {
        if (tid < 16) nxt[tid] = 0ULL;
        if (tid == 0) misc[0] = 0;
        __syncthreads();
        u64 acc = 0;
        for (int i = i0; i < nv; i += 64)
            if (!((cur[i >> 6] >> (i & 63)) & 1ULL)) acc |= mask[i * 16 + w];
        if (acc) atomicOr(&nxt[w], acc);
        __syncthreads();
        if (tid < 16) {
            if (nxt[tid] != cur[tid]) misc[0] = 1;
            cur[tid] = nxt[tid];
        }
        __syncthreads();
        if (!misc[0]) break;
    }

    // ---- phase 7: compact kept (order preserved; vpos monotone in tid) ----
    int keepf = valid && !((cur[vpos >> 6] >> (vpos & 63)) & 1ULL);
    int ktot;
    int kpos = bscan(keepf, misc + 8, tid, &ktot);
    if (keepf) {
        g_kb[bl][kpos] = make_float4(cx1, cy1, cx2, cy2);
        g_kkey[bl][kpos] = sigbits;
    }
    if (tid == 0) g_kcnt[bl] = ktot;

    // ---- phase 8: last block of batch runs the rank-merge -----------------
    __threadfence();
    if (tid == 0) misc[64] = (atomicAdd(&g_done[b], 1) == NLVL - 1);
    __syncthreads();
    if (!misc[64]) return;
    __threadfence();

    int* cnt = misc + 66;    // 5
    int* off = misc + 72;    // 6
    if (tid < NLVL) cnt[tid] = g_kcnt[b * NLVL + tid];
    __syncthreads();
    if (tid == 0) {
        int s = 0;
        for (int q = 0; q < NLVL; q++) { off[q] = s; s += cnt[q]; }
        off[NLVL] = s;
        g_done[b] = 0;       // ready for next replay
    }
    __syncthreads();
    int total = off[NLVL];
    for (int l2 = 0; l2 < NLVL; l2++)
        for (int p = tid; p < cnt[l2]; p += 1024)
            skeys[l2 * NPAD + p] = g_kkey[b * NLVL + l2][p];
    __syncthreads();

    for (int j = total + tid; j < 1000; j += 1024)
        out[b * 1000 + j] = make_float4(0.f, 0.f, 0.f, 0.f);

    // rank(l,p,s) = p + sum_{l'<l} #{key' >= s} + sum_{l'>l} #{key' > s}
    for (int e = tid; e < total; e += 1024) {
        int le = 0;
        while (le < NLVL - 1 && e >= off[le + 1]) le++;
        int p = e - off[le];
        u32 s = skeys[le * NPAD + p];
        int rank = p;
#pragma unroll
        for (int l2 = 0; l2 < NLVL; l2++) {
            if (l2 == le) continue;
            const u32* a = skeys + l2 * NPAD;
            int lo = 0, hi = cnt[l2];
            if (l2 < le) {
                while (lo < hi) { int mid = (lo + hi) >> 1; if (a[mid] < s) hi = mid; else lo = mid + 1; }
            } else {
                while (lo < hi) { int mid = (lo + hi) >> 1; if (a[mid] <= s) hi = mid; else lo = mid + 1; }
            }
            rank += lo;
        }
        if (rank < 1000)
            out[b * 1000 + rank] = g_kb[b * NLVL + le][p];
    }
}

static bool msz(const int* s, const int* ref) {
    for (int i = 0; i < 11; i++) if (s[i] != ref[i]) return false;
    return true;
}

extern "C" void kernel_launch(void* const* d_in, const int* in_sizes, int n_in,
                              void* d_out, int out_size) {
    const float *o[5], *dl[5], *anch;
    static const int inter[11] = {960000, 3840000, 240000, 960000, 60000,
                                  240000, 15000, 60000, 4056, 16224, 639528};
    static const int alpha[11] = {639528, 3840000, 960000, 240000, 60000,
                                  16224, 960000, 240000, 60000, 15000, 4056};
    if (n_in >= 11 && msz(in_sizes, inter)) {
        for (int i = 0; i < 5; i++) { o[i] = (const float*)d_in[2 * i]; dl[i] = (const float*)d_in[2 * i + 1]; }
        anch = (const float*)d_in[10];
    } else if (n_in >= 11 && msz(in_sizes, alpha)) {
        anch = (const float*)d_in[0];
        for (int i = 0; i < 5; i++) { dl[i] = (const float*)d_in[1 + i]; o[i] = (const float*)d_in[6 + i]; }
    } else {
        for (int i = 0; i < 5; i++) { o[i] = (const float*)d_in[i]; dl[i] = (const float*)d_in[5 + i]; }
        anch = (const float*)d_in[10];
    }
    (void)out_size;

    static int attr_done = 0;
    if (!attr_done) {
        cudaFuncSetAttribute(k_proc, cudaFuncAttributeMaxDynamicSharedMemorySize, SMEMP);
        attr_done = 1;
    }

    k_histthresh<<<dim3(NBL, NCH), 256>>>(o[0], o[1], o[2], o[3]);
    k_compact<<<dim3(NBL, NCH), 256>>>(o[0], o[1], o[2], o[3]);
    k_proc<<<NBL, 1024, SMEMP>>>(o[4], dl[0], dl[1], dl[2], dl[3], dl[4], anch,
                                 (float4*)d_out);
}

// round 8
// speedup vs baseline: 1.8268x; 1.8268x over previous
#include <cuda_runtime.h>
#include <cstdint>

typedef unsigned long long u64;
typedef unsigned int u32;

#define NBATCH 8
#define NLVL 5
#define NBL 40
#define NCH 16
#define NPAD 1024
#define CAND 4096
#define IMGSZ 800.0f
#define CLIPV 4.135166556742356f

__constant__ int c_h[NLVL]   = {200, 100, 50, 25, 13};
__constant__ int c_n[NLVL]   = {120000, 30000, 7500, 1875, 507};
__constant__ int c_off[NLVL] = {0, 120000, 150000, 157500, 159375};
__constant__ int c_k[NLVL]   = {1000, 1000, 1000, 1000, 507};

__device__ u32    g_hist16[NBL][NCH][4096];
__device__ u32    g_B[NBL];
__device__ int    g_ccnt[NBL];
__device__ int    g_arrive[NBL];      // zero-init; reset by consumer
__device__ int    g_done[NBATCH];     // zero-init; reset by consumer
__device__ u64    g_cand[NBL][CAND];
__device__ float4 g_kb  [NBL][NPAD];
__device__ u32    g_kkey[NBL][NPAD];
__device__ int    g_kcnt[NBL];

__device__ __forceinline__ u32 fkey(float f) {
    u32 u = __float_as_uint(f);
    return u ^ ((u32)((int)u >> 31) | 0x80000000u);
}
__device__ __forceinline__ float unfkey(u32 enc) {
    u32 u = (enc & 0x80000000u) ? (enc ^ 0x80000000u) : ~enc;
    return __uint_as_float(u);
}

__device__ __forceinline__ int bscan(int v, int* ws, int tid, int* total) {
    int lane = tid & 31, wid = tid >> 5;
    int x = v;
#pragma unroll
    for (int o = 1; o < 32; o <<= 1) {
        int y = __shfl_up_sync(~0u, x, o);
        if (lane >= o) x += y;
    }
    if (lane == 31) ws[wid] = x;
    __syncthreads();
    if (wid == 0) {
        int y = ws[lane];
#pragma unroll
        for (int o = 1; o < 32; o <<= 1) {
            int z = __shfl_up_sync(~0u, y, o);
            if (lane >= o) y += z;
        }
        ws[lane] = y;
    }
    __syncthreads();
    int base = wid ? ws[wid - 1] : 0;
    int tot = ws[31];
    __syncthreads();
    *total = tot;
    return base + x - v;
}

__device__ __forceinline__ void bitonic_desc(u64* a, int n, int tid) {
    for (int sz = 2; sz <= n; sz <<= 1)
        for (int st = sz >> 1; st >= 1; st >>= 1) {
            __syncthreads();
            for (int t = tid; t < (n >> 1); t += 1024) {
                int i = t + (t & ~(st - 1));
                int j = i + st;
                u64 x = a[i], y = a[j];
                if (((i & sz) == 0) ? (x < y) : (x > y)) { a[i] = y; a[j] = x; }
            }
        }
    __syncthreads();
}

// ---- K0: chunk histograms; last-arriving chunk block picks threshold ------
__global__ void k_histthresh(const float* __restrict__ o0, const float* __restrict__ o1,
                             const float* __restrict__ o2, const float* __restrict__ o3) {
    int bl = blockIdx.x, c = blockIdx.y, tid = threadIdx.x;
    int b = bl / NLVL, l = bl % NLVL;
    if (l == 4) return;
    int h2 = c_h[l] * c_h[l], n = c_n[l];
    const float* ob = ((l == 0) ? o0 : (l == 1) ? o1 : (l == 2) ? o2 : o3) + (size_t)b * 3 * h2;
    __shared__ u32 hist[4096];
    __shared__ int misc[160];
    __shared__ int lastf;
    for (int q = tid; q < 4096; q += 256) hist[q] = 0;
    __syncthreads();
    if (l < 3) {
        const float4* ob4 = (const float4*)ob;
        int n4 = n >> 2, cs = (n4 + NCH - 1) / NCH;
        int qs = c * cs, qe = min(qs + cs, n4);
        for (int q = qs + tid; q < qe; q += 256) {
            float4 v = ob4[q];
            atomicAdd(&hist[fkey(v.x) >> 20], 1u);
            atomicAdd(&hist[fkey(v.y) >> 20], 1u);
            atomicAdd(&hist[fkey(v.z) >> 20], 1u);
            atomicAdd(&hist[fkey(v.w) >> 20], 1u);
        }
    } else {
        int cs = (n + NCH - 1) / NCH;
        int qs = c * cs, qe = min(qs + cs, n);
        for (int q = qs + tid; q < qe; q += 256)
            atomicAdd(&hist[fkey(ob[q]) >> 20], 1u);
    }
    __syncthreads();
    for (int q = tid; q < 4096; q += 256) g_hist16[bl][c][q] = hist[q];
    __threadfence();
    if (tid == 0) lastf = (atomicAdd(&g_arrive[bl], 1) == NCH - 1);
    __syncthreads();
    if (!lastf) return;
    __threadfence();
    for (int j = tid; j < 4096; j += 256) {
        u32 s = 0;
#pragma unroll
        for (int c2 = 0; c2 < NCH; c2++) s += g_hist16[bl][c2][j];
        hist[j] = s;
    }
    __syncthreads();
    if (tid < 128) {
        u32 s = 0;
        for (int q = 0; q < 32; q++) s += hist[tid * 32 + q];
        misc[tid + 8] = (int)s;
    }
    __syncthreads();
    if (tid == 0) {
        int kk = c_k[l];
        int acc = 0, cc;
        for (cc = 127; cc > 0; cc--) {
            if (acc + misc[cc + 8] >= kk) break;
            acc += misc[cc + 8];
        }
        int bsel = cc * 32;
        for (int q = 31; q >= 0; q--) {
            int hv = (int)hist[cc * 32 + q];
            if (acc + hv >= kk) { bsel = cc * 32 + q; break; }
            acc += hv;
        }
        g_B[bl] = (u32)bsel;
        g_ccnt[bl] = 0;
        g_arrive[bl] = 0;   // ready for next replay
    }
}

// ---- K1: compact candidates >= threshold bucket ---------------------------
__global__ void k_compact(const float* __restrict__ o0, const float* __restrict__ o1,
                          const float* __restrict__ o2, const float* __restrict__ o3) {
    int bl = blockIdx.x, c = blockIdx.y, tid = threadIdx.x;
    int b = bl / NLVL, l = bl % NLVL;
    if (l == 4) return;
    int h2 = c_h[l] * c_h[l], n = c_n[l];
    const float* ob = ((l == 0) ? o0 : (l == 1) ? o1 : (l == 2) ? o2 : o3) + (size_t)b * 3 * h2;
    u32 B = g_B[bl];
    if (l < 3) {
        const float4* ob4 = (const float4*)ob;
        int n4 = n >> 2, cs = (n4 + NCH - 1) / NCH;
        int qs = c * cs, qe = min(qs + cs, n4);
        for (int q = qs + tid; q < qe; q += 256) {
            float4 v = ob4[q];
            float vv[4] = {v.x, v.y, v.z, v.w};
#pragma unroll
            for (int e4 = 0; e4 < 4; e4++) {
                u32 u = fkey(vv[e4]);
                if ((u >> 20) >= B) {
                    int pos = atomicAdd(&g_ccnt[bl], 1);
                    if (pos < CAND) {
                        int i0 = 4 * q + e4;
                        int a = (i0 >= h2) + (i0 >= 2 * h2);
                        int p = i0 - a * h2;
                        g_cand[bl][pos] = ((u64)u << 32) | (u32)(~(u32)(p * 3 + a));
                    }
                }
            }
        }
    } else {
        int cs = (n + NCH - 1) / NCH;
        int qs = c * cs, qe = min(qs + cs, n);
        for (int q = qs + tid; q < qe; q += 256) {
            u32 u = fkey(ob[q]);
            if ((u >> 20) >= B) {
                int pos = atomicAdd(&g_ccnt[bl], 1);
                if (pos < CAND) {
                    int a = (q >= h2) + (q >= 2 * h2);
                    int p = q - a * h2;
                    g_cand[bl][pos] = ((u64)u << 32) | (u32)(~(u32)(p * 3 + a));
                }
            }
        }
    }
}

// ---- K2: fused sort -> decode -> mask -> NMS -> compact -> merge ----------
// smem layout (bytes):
//   mask  [0, 131072)   u64[1024][16]   (aliased: cand u64[4096] in [0,32768),
//                                        skeys u32[5][1024] in merge phase)
//   obox  [131072, 147456) float4[1024]
//   oar   [147456, 151552) float[1024]
//   cur   [151552, 151680) u64[16]
//   nxt   [151680, 151808) u64[16]
//   misc  [151808, 152576) int[192]
#define SMEMP 152576

__global__ __launch_bounds__(1024, 1)
void k_proc(const float* __restrict__ o4,
            const float* __restrict__ dl0, const float* __restrict__ dl1,
            const float* __restrict__ dl2, const float* __restrict__ dl3,
            const float* __restrict__ dl4, const float* __restrict__ anchors,
            float4* __restrict__ out) {
    extern __shared__ unsigned char sm[];
    u64*    mask = (u64*)sm;
    u64*    cand = (u64*)sm;
    float4* obox = (float4*)(sm + 131072);
    float*  oar  = (float*)(sm + 147456);
    u64*    cur  = (u64*)(sm + 151552);
    u64*    nxt  = cur + 16;
    int*    misc = (int*)(sm + 151808);
    u32*    skeys = (u32*)sm;   // merge phase only

    int tid = threadIdx.x;
    int bl = blockIdx.x, b = bl / NLVL, l = bl % NLVL;
    int h = c_h[l], n = c_n[l], kk = c_k[l], h2 = h * h;

    // ---- phase 1: load candidates ----
    int S;
    if (l == 4) {
        const float* ob = o4 + (size_t)b * 3 * h2;
        for (int j = tid; j < NPAD; j += 1024) {
            u64 e = 0ULL;
            if (j < n) {
                int p = j / 3, a = j - p * 3, y = p / h, x = p - y * h;
                float v = ob[(a * h + y) * h + x];
                e = ((u64)fkey(v) << 32) | (u32)(~(u32)j);
            }
            cand[j] = e;
        }
        S = 1024;
    } else {
        int m = g_ccnt[bl];
        if (m > CAND) m = CAND;
        S = (m <= 1024) ? 1024 : ((m <= 2048) ? 2048 : 4096);
        for (int q = tid; q < S; q += 1024)
            cand[q] = (q < m) ? g_cand[bl][q] : 0ULL;
    }
    __syncthreads();

    // ---- phase 2: exact lax.top_k order ----
    bitonic_desc(cand, S, tid);

    // ---- phase 3: decode + clip + validity (registers) ----
    float C = 4096.0f * (float)l;
    const float* dl = (l == 0) ? dl0 : (l == 1) ? dl1 : (l == 2) ? dl2 : (l == 3) ? dl3 : dl4;
    int valid = 0;
    float cx1 = 0.f, cy1 = 0.f, cx2 = 0.f, cy2 = 0.f;
    u32 sigbits = 0;
    if (tid < kk) {
        u64 e = cand[tid];
        u32 idx = ~(u32)(e & 0xFFFFFFFFu);
        float logit = unfkey((u32)(e >> 32));
        sigbits = __float_as_uint(__fdiv_rn(1.0f, 1.0f + expf(-logit)));
        int p = (int)(idx / 3u), a = (int)idx - p * 3;
        int y = p / h, x = p - y * h;
        int gi = c_off[l] + (int)idx;
        float ax1 = anchors[4 * gi], ay1 = anchors[4 * gi + 1];
        float ax2 = anchors[4 * gi + 2], ay2 = anchors[4 * gi + 3];
        float wa = ax2 - ax1, ha = ay2 - ay1;
        float cxa = ax1 + 0.5f * wa, cya = ay1 + 0.5f * ha;
        int dbase = ((b * 12 + a * 4) * h + y) * h + x;
        float dx = dl[dbase], dy = dl[dbase + h2];
        float dw = fminf(dl[dbase + 2 * h2], CLIPV);
        float dh = fminf(dl[dbase + 3 * h2], CLIPV);
        float cx = dx * wa + cxa, cy = dy * ha + cya;
        float pw = expf(dw) * wa, ph = expf(dh) * ha;
        cx1 = fminf(fmaxf(cx - 0.5f * pw, 0.0f), IMGSZ);
        cy1 = fminf(fmaxf(cy - 0.5f * ph, 0.0f), IMGSZ);
        cx2 = fminf(fmaxf(cx + 0.5f * pw, 0.0f), IMGSZ);
        cy2 = fminf(fmaxf(cy + 0.5f * ph, 0.0f), IMGSZ);
        valid = ((cx2 - cx1) >= 1e-3f && (cy2 - cy1) >= 1e-3f) ? 1 : 0;
    }
    __syncthreads();   // all cand reads done; cand region may be reused below

    // ---- phase 4: stable compaction of valid candidates ----
    int nv;
    int vpos = bscan(valid, misc + 8, tid, &nv);
    if (valid) {
        float xo1 = cx1 + C, yo1 = cy1 + C, xo2 = cx2 + C, yo2 = cy2 + C;
        obox[vpos] = make_float4(xo1, yo1, xo2, yo2);
        oar[vpos] = (xo2 - xo1) * (yo2 - yo1);
    }
    __syncthreads();

    // ---- phase 5: IoU mask in shared (broadcast-friendly mapping) ----
    // 64-thread group per j-column w: inner jj loop uniform across warp ->
    // obox[j0+jj]/oar[j0+jj] are warp-broadcast LDS reads (conflict-free).
    {
        int w = tid >> 6;        // 0..15
        int i00 = tid & 63;
        int j0 = w << 6;
        int jend = min(j0 + 64, nv) - j0;   // <= 64
        for (int i = i00; i < nv; i += 64) {
            u64 mword = 0;
            if (jend > 0 && i < j0 + jend) {  // rows entirely right of column skip nothing; rows left produce bits
                float4 bi = obox[i];
                float ai = oar[i];
                int jsrel = max(j0, i + 1) - j0;
                for (int jj = jsrel; jj < jend; jj++) {
                    float4 bj = obox[j0 + jj];
                    float lx = fmaxf(bi.x, bj.x), ly = fmaxf(bi.y, bj.y);
                    float rx = fminf(bi.z, bj.z), ry = fminf(bi.w, bj.w);
                    float ww2 = rx - lx, hh2 = ry - ly;
                    if (ww2 > 0.0f && hh2 > 0.0f) {
                        float inter = ww2 * hh2;
                        float uni = ai + oar[j0 + jj] - inter + 1e-9f;
                        if (__fdiv_rn(inter, uni) > 0.7f) mword |= 1ULL << jj;
                    }
                }
            } else if (jend > 0 && i >= j0) {
                // i beyond column end: no bits (j <= i)
            } else if (jend > 0) {
                // i < j0: full column
                float4 bi = obox[i];
                float ai = oar[i];
                for (int jj = 0; jj < jend; jj++) {
                    float4 bj = obox[j0 + jj];
                    float lx = fmaxf(bi.x, bj.x), ly = fmaxf(bi.y, bj.y);
                    float rx = fminf(bi.z, bj.z), ry = fminf(bi.w, bj.w);
                    float ww2 = rx - lx, hh2 = ry - ly;
                    if (ww2 > 0.0f && hh2 > 0.0f) {
                        float inter = ww2 * hh2;
                        float uni = ai + oar[j0 + jj] - inter + 1e-9f;
                        if (__fdiv_rn(inter, uni) > 0.7f) mword |= 1ULL << jj;
                    }
                }
            }
            mask[(i << 4) + w] = mword;
        }
    }
    if (tid < 16) cur[tid] = 0ULL;
    __syncthreads();

    // ---- phase 6: fixed-point greedy NMS (unique fixed point == greedy) ----
    int w6 = tid & 15, i06 = tid >> 4;
    for (int it = 0; it < NPAD; it++) {
        if (tid < 16) nxt[tid] = 0ULL;
        if (tid == 0) misc[0] = 0;
        __syncthreads();
        u64 acc = 0;
        for (int i = i06; i < nv; i += 64)
            if (!((cur[i >> 6] >> (i & 63)) & 1ULL)) acc |= mask[i * 16 + w6];
        if (acc) atomicOr(&nxt[w6], acc);
        __syncthreads();
        if (tid < 16) {
            if (nxt[tid] != cur[tid]) misc[0] = 1;
            cur[tid] = nxt[tid];
        }
        __syncthreads();
        if (!misc[0]) break;
    }

    // ---- phase 7: compact kept (order preserved; vpos monotone in tid) ----
    int keepf = valid && !((cur[vpos >> 6] >> (vpos & 63)) & 1ULL);
    int ktot;
    int kpos = bscan(keepf, misc + 8, tid, &ktot);
    if (keepf) {
        g_kb[bl][kpos] = make_float4(cx1, cy1, cx2, cy2);
        g_kkey[bl][kpos] = sigbits;
    }
    if (tid == 0) g_kcnt[bl] = ktot;

    // ---- phase 8: last block of batch runs the rank-merge -----------------
    __threadfence();
    if (tid == 0) misc[64] = (atomicAdd(&g_done[b], 1) == NLVL - 1);
    __syncthreads();
    if (!misc[64]) return;
    __threadfence();

    int* cnt = misc + 66;
    int* off = misc + 72;
    if (tid < NLVL) cnt[tid] = g_kcnt[b * NLVL + tid];
    __syncthreads();
    if (tid == 0) {
        int s = 0;
        for (int q = 0; q < NLVL; q++) { off[q] = s; s += cnt[q]; }
        off[NLVL] = s;
        g_done[b] = 0;       // ready for next replay
    }
    __syncthreads();
    int total = off[NLVL];
    for (int l2 = 0; l2 < NLVL; l2++)
        for (int p = tid; p < cnt[l2]; p += 1024)
            skeys[l2 * NPAD + p] = g_kkey[b * NLVL + l2][p];
    __syncthreads();

    for (int j = total + tid; j < 1000; j += 1024)
        out[b * 1000 + j] = make_float4(0.f, 0.f, 0.f, 0.f);

    // rank(l,p,s) = p + sum_{l'<l} #{key' >= s} + sum_{l'>l} #{key' > s}
    for (int e = tid; e < total; e += 1024) {
        int le = 0;
        while (le < NLVL - 1 && e >= off[le + 1]) le++;
        int p = e - off[le];
        u32 s = skeys[le * NPAD + p];
        int rank = p;
#pragma unroll
        for (int l2 = 0; l2 < NLVL; l2++) {
            if (l2 == le) continue;
            const u32* a = skeys + l2 * NPAD;
            int lo = 0, hi = cnt[l2];
            if (l2 < le) {
                while (lo < hi) { int mid = (lo + hi) >> 1; if (a[mid] < s) hi = mid; else lo = mid + 1; }
            } else {
                while (lo < hi) { int mid = (lo + hi) >> 1; if (a[mid] <= s) hi = mid; else lo = mid + 1; }
            }
            rank += lo;
        }
        if (rank < 1000)
            out[b * 1000 + rank] = g_kb[b * NLVL + le][p];
    }
}

static bool msz(const int* s, const int* ref) {
    for (int i = 0; i < 11; i++) if (s[i] != ref[i]) return false;
    return true;
}

extern "C" void kernel_launch(void* const* d_in, const int* in_sizes, int n_in,
                              void* d_out, int out_size) {
    const float *o[5], *dl[5], *anch;
    static const int inter[11] = {960000, 3840000, 240000, 960000, 60000,
                                  240000, 15000, 60000, 4056, 16224, 639528};
    static const int alpha[11] = {639528, 3840000, 960000, 240000, 60000,
                                  16224, 960000, 240000, 60000, 15000, 4056};
    if (n_in >= 11 && msz(in_sizes, inter)) {
        for (int i = 0; i < 5; i++) { o[i] = (const float*)d_in[2 * i]; dl[i] = (const float*)d_in[2 * i + 1]; }
        anch = (const float*)d_in[10];
    } else if (n_in >= 11 && msz(in_sizes, alpha)) {
        anch = (const float*)d_in[0];
        for (int i = 0; i < 5; i++) { dl[i] = (const float*)d_in[1 + i]; o[i] = (const float*)d_in[6 + i]; }
    } else {
        for (int i = 0; i < 5; i++) { o[i] = (const float*)d_in[i]; dl[i] = (const float*)d_in[5 + i]; }
        anch = (const float*)d_in[10];
    }
    (void)out_size;

    static int attr_done = 0;
    if (!attr_done) {
        cudaFuncSetAttribute(k_proc, cudaFuncAttributeMaxDynamicSharedMemorySize, SMEMP);
        attr_done = 1;
    }

    k_histthresh<<<dim3(NBL, NCH), 256>>>(o[0], o[1], o[2], o[3]);
    k_compact<<<dim3(NBL, NCH), 256>>>(o[0], o[1], o[2], o[3]);
    k_proc<<<NBL, 1024, SMEMP>>>(o[4], dl[0], dl[1], dl[2], dl[3], dl[4], anch,
                                 (float4*)d_out);
}

// round 9
// speedup vs baseline: 3.0250x; 1.6559x over previous
#include <cuda_runtime.h>
#include <cstdint>

typedef unsigned long long u64;
typedef unsigned int u32;

#define NBATCH 8
#define NLVL 5
#define NBL 40
#define NCH 16
#define NPAD 1024
#define CAND 4096
#define IMGSZ 800.0f
#define CLIPV 4.135166556742356f

__constant__ int c_h[NLVL]   = {200, 100, 50, 25, 13};
__constant__ int c_n[NLVL]   = {120000, 30000, 7500, 1875, 507};
__constant__ int c_off[NLVL] = {0, 120000, 150000, 157500, 159375};
__constant__ int c_k[NLVL]   = {1000, 1000, 1000, 1000, 507};

__device__ u32    g_hist16[NBL][NCH][4096];
__device__ u32    g_B[NBL];
__device__ int    g_ccnt[NBL];
__device__ int    g_arrive[NBL];      // zero-init; reset by consumer
__device__ u64    g_cand[NBL][CAND];
__device__ float4 g_obox[NBL][NPAD];
__device__ float  g_oar [NBL][NPAD];
__device__ float4 g_ubox[NBL][NPAD];
__device__ u32    g_sig [NBL][NPAD];
__device__ int    g_nv  [NBL];
__device__ u64    g_mask[NBL][NPAD][16];
__device__ float4 g_kb  [NBL][NPAD];
__device__ u32    g_kkey[NBL][NPAD];
__device__ int    g_kcnt[NBL];

__device__ __forceinline__ u32 fkey(float f) {
    u32 u = __float_as_uint(f);
    return u ^ ((u32)((int)u >> 31) | 0x80000000u);
}
__device__ __forceinline__ float unfkey(u32 enc) {
    u32 u = (enc & 0x80000000u) ? (enc ^ 0x80000000u) : ~enc;
    return __uint_as_float(u);
}

__device__ __forceinline__ int bscan(int v, int* ws, int tid, int* total) {
    int lane = tid & 31, wid = tid >> 5;
    int x = v;
#pragma unroll
    for (int o = 1; o < 32; o <<= 1) {
        int y = __shfl_up_sync(~0u, x, o);
        if (lane >= o) x += y;
    }
    if (lane == 31) ws[wid] = x;
    __syncthreads();
    if (wid == 0) {
        int y = ws[lane];
#pragma unroll
        for (int o = 1; o < 32; o <<= 1) {
            int z = __shfl_up_sync(~0u, y, o);
            if (lane >= o) y += z;
        }
        ws[lane] = y;
    }
    __syncthreads();
    int base = wid ? ws[wid - 1] : 0;
    int tot = ws[31];
    __syncthreads();
    *total = tot;
    return base + x - v;
}

// Hybrid-barrier bitonic sort, descending. For st <= 32 every exchange stays
// within one warp's private 64-element chunk (i = t + (t & ~(st-1)) keeps
// i,j in [64w, 64w+64) for threads 32w..32w+31, for any pair-batch offset
// multiple of 1024) -> __syncwarp suffices. Block barrier only when the
// current or previous stage crossed chunks (st >= 64). Comparator identical
// to the proven version -> bit-identical output.
__device__ __forceinline__ void bitonic_desc(u64* a, int n, int tid) {
    bool prev_big = true;   // initial fill was block-wide
    for (int sz = 2; sz <= n; sz <<= 1)
        for (int st = sz >> 1; st >= 1; st >>= 1) {
            bool big = (st >= 64);
            if (big || prev_big) __syncthreads(); else __syncwarp();
            prev_big = big;
            for (int t = tid; t < (n >> 1); t += 1024) {
                int i = t + (t & ~(st - 1));
                int j = i + st;
                u64 x = a[i], y = a[j];
                if (((i & sz) == 0) ? (x < y) : (x > y)) { a[i] = y; a[j] = x; }
            }
        }
    __syncthreads();
}

// ---- K0: chunk histograms; last-arriving chunk block picks threshold ------
__global__ void k_histthresh(const float* __restrict__ o0, const float* __restrict__ o1,
                             const float* __restrict__ o2, const float* __restrict__ o3) {
    int bl = blockIdx.x, c = blockIdx.y, tid = threadIdx.x;
    int b = bl / NLVL, l = bl % NLVL;
    if (l == 4) return;
    int h2 = c_h[l] * c_h[l], n = c_n[l];
    const float* ob = ((l == 0) ? o0 : (l == 1) ? o1 : (l == 2) ? o2 : o3) + (size_t)b * 3 * h2;
    __shared__ u32 hist[4096];
    __shared__ int misc[160];
    __shared__ int lastf;
    for (int q = tid; q < 4096; q += 256) hist[q] = 0;
    __syncthreads();
    if (l < 3) {
        const float4* ob4 = (const float4*)ob;
        int n4 = n >> 2, cs = (n4 + NCH - 1) / NCH;
        int qs = c * cs, qe = min(qs + cs, n4);
        for (int q = qs + tid; q < qe; q += 256) {
            float4 v = ob4[q];
            atomicAdd(&hist[fkey(v.x) >> 20], 1u);
            atomicAdd(&hist[fkey(v.y) >> 20], 1u);
            atomicAdd(&hist[fkey(v.z) >> 20], 1u);
            atomicAdd(&hist[fkey(v.w) >> 20], 1u);
        }
    } else {
        int cs = (n + NCH - 1) / NCH;
        int qs = c * cs, qe = min(qs + cs, n);
        for (int q = qs + tid; q < qe; q += 256)
            atomicAdd(&hist[fkey(ob[q]) >> 20], 1u);
    }
    __syncthreads();
    for (int q = tid; q < 4096; q += 256) g_hist16[bl][c][q] = hist[q];
    __threadfence();
    if (tid == 0) lastf = (atomicAdd(&g_arrive[bl], 1) == NCH - 1);
    __syncthreads();
    if (!lastf) return;
    __threadfence();
    for (int j = tid; j < 4096; j += 256) {
        u32 s = 0;
#pragma unroll
        for (int c2 = 0; c2 < NCH; c2++) s += g_hist16[bl][c2][j];
        hist[j] = s;
    }
    __syncthreads();
    if (tid < 128) {
        u32 s = 0;
        for (int q = 0; q < 32; q++) s += hist[tid * 32 + q];
        misc[tid + 8] = (int)s;
    }
    __syncthreads();
    if (tid == 0) {
        int kk = c_k[l];
        int acc = 0, cc;
        for (cc = 127; cc > 0; cc--) {
            if (acc + misc[cc + 8] >= kk) break;
            acc += misc[cc + 8];
        }
        int bsel = cc * 32;
        for (int q = 31; q >= 0; q--) {
            int hv = (int)hist[cc * 32 + q];
            if (acc + hv >= kk) { bsel = cc * 32 + q; break; }
            acc += hv;
        }
        g_B[bl] = (u32)bsel;
        g_ccnt[bl] = 0;
        g_arrive[bl] = 0;   // ready for next replay
    }
}

// ---- K1: compact candidates >= threshold bucket ---------------------------
__global__ void k_compact(const float* __restrict__ o0, const float* __restrict__ o1,
                          const float* __restrict__ o2, const float* __restrict__ o3) {
    int bl = blockIdx.x, c = blockIdx.y, tid = threadIdx.x;
    int b = bl / NLVL, l = bl % NLVL;
    if (l == 4) return;
    int h2 = c_h[l] * c_h[l], n = c_n[l];
    const float* ob = ((l == 0) ? o0 : (l == 1) ? o1 : (l == 2) ? o2 : o3) + (size_t)b * 3 * h2;
    u32 B = g_B[bl];
    if (l < 3) {
        const float4* ob4 = (const float4*)ob;
        int n4 = n >> 2, cs = (n4 + NCH - 1) / NCH;
        int qs = c * cs, qe = min(qs + cs, n4);
        for (int q = qs + tid; q < qe; q += 256) {
            float4 v = ob4[q];
            float vv[4] = {v.x, v.y, v.z, v.w};
#pragma unroll
            for (int e4 = 0; e4 < 4; e4++) {
                u32 u = fkey(vv[e4]);
                if ((u >> 20) >= B) {
                    int pos = atomicAdd(&g_ccnt[bl], 1);
                    if (pos < CAND) {
                        int i0 = 4 * q + e4;
                        int a = (i0 >= h2) + (i0 >= 2 * h2);
                        int p = i0 - a * h2;
                        g_cand[bl][pos] = ((u64)u << 32) | (u32)(~(u32)(p * 3 + a));
                    }
                }
            }
        }
    } else {
        int cs = (n + NCH - 1) / NCH;
        int qs = c * cs, qe = min(qs + cs, n);
        for (int q = qs + tid; q < qe; q += 256) {
            u32 u = fkey(ob[q]);
            if ((u >> 20) >= B) {
                int pos = atomicAdd(&g_ccnt[bl], 1);
                if (pos < CAND) {
                    int a = (q >= h2) + (q >= 2 * h2);
                    int p = q - a * h2;
                    g_cand[bl][pos] = ((u64)u << 32) | (u32)(~(u32)(p * 3 + a));
                }
            }
        }
    }
}

// ---- K2: per (b,l): sort candidates -> decode -> validity compact ---------
#define SMEM3 (CAND * 8 + 1024)
__global__ __launch_bounds__(1024, 1)
void k_sortdecode(const float* __restrict__ o4,
                  const float* __restrict__ dl0, const float* __restrict__ dl1,
                  const float* __restrict__ dl2, const float* __restrict__ dl3,
                  const float* __restrict__ dl4, const float* __restrict__ anchors) {
    extern __shared__ unsigned char sm[];
    u64* cand = (u64*)sm;
    int* misc = (int*)(sm + CAND * 8);
    int tid = threadIdx.x;
    int bl = blockIdx.x, b = bl / NLVL, l = bl % NLVL;
    int h = c_h[l], n = c_n[l], kk = c_k[l], h2 = h * h;

    int S;
    if (l == 4) {
        const float* ob = o4 + (size_t)b * 3 * h2;
        for (int j = tid; j < NPAD; j += 1024) {
            u64 e = 0ULL;
            if (j < n) {
                int p = j / 3, a = j - p * 3, y = p / h, x = p - y * h;
                float v = ob[(a * h + y) * h + x];
                e = ((u64)fkey(v) << 32) | (u32)(~(u32)j);
            }
            cand[j] = e;
        }
        S = 1024;
    } else {
        int m = g_ccnt[bl];
        if (m > CAND) m = CAND;
        S = (m <= 1024) ? 1024 : ((m <= 2048) ? 2048 : 4096);
        for (int q = tid; q < S; q += 1024)
            cand[q] = (q < m) ? g_cand[bl][q] : 0ULL;
    }

    bitonic_desc(cand, S, tid);   // (key desc, idx asc) == lax.top_k order

    float C = 4096.0f * (float)l;
    const float* dl = (l == 0) ? dl0 : (l == 1) ? dl1 : (l == 2) ? dl2 : (l == 3) ? dl3 : dl4;
    int valid = 0;
    float cx1 = 0.f, cy1 = 0.f, cx2 = 0.f, cy2 = 0.f;
    u32 sigbits = 0;
    if (tid < kk) {
        u64 e = cand[tid];
        u32 idx = ~(u32)(e & 0xFFFFFFFFu);
        float logit = unfkey((u32)(e >> 32));
        sigbits = __float_as_uint(__fdiv_rn(1.0f, 1.0f + expf(-logit)));
        int p = (int)(idx / 3u), a = (int)idx - p * 3;
        int y = p / h, x = p - y * h;
        int gi = c_off[l] + (int)idx;
        float ax1 = anchors[4 * gi], ay1 = anchors[4 * gi + 1];
        float ax2 = anchors[4 * gi + 2], ay2 = anchors[4 * gi + 3];
        float wa = ax2 - ax1, ha = ay2 - ay1;
        float cxa = ax1 + 0.5f * wa, cya = ay1 + 0.5f * ha;
        int dbase = ((b * 12 + a * 4) * h + y) * h + x;
        float dx = dl[dbase], dy = dl[dbase + h2];
        float dw = fminf(dl[dbase + 2 * h2], CLIPV);
        float dh = fminf(dl[dbase + 3 * h2], CLIPV);
        float cx = dx * wa + cxa, cy = dy * ha + cya;
        float pw = expf(dw) * wa, ph = expf(dh) * ha;
        cx1 = fminf(fmaxf(cx - 0.5f * pw, 0.0f), IMGSZ);
        cy1 = fminf(fmaxf(cy - 0.5f * ph, 0.0f), IMGSZ);
        cx2 = fminf(fmaxf(cx + 0.5f * pw, 0.0f), IMGSZ);
        cy2 = fminf(fmaxf(cy + 0.5f * ph, 0.0f), IMGSZ);
        valid = ((cx2 - cx1) >= 1e-3f && (cy2 - cy1) >= 1e-3f) ? 1 : 0;
    }
    __syncthreads();

    int nv;
    int vpos = bscan(valid, misc, tid, &nv);
    if (valid) {
        float xo1 = cx1 + C, yo1 = cy1 + C, xo2 = cx2 + C, yo2 = cy2 + C;
        g_obox[bl][vpos] = make_float4(xo1, yo1, xo2, yo2);
        g_oar[bl][vpos] = (xo2 - xo1) * (yo2 - yo1);
        g_ubox[bl][vpos] = make_float4(cx1, cy1, cx2, cy2);
        g_sig[bl][vpos] = sigbits;
    }
    if (tid == 0) g_nv[bl] = nv;
}

// ---- K3: mask builder, full-chip parallel: grid (40, 16) x 256 -----------
__global__ void k_mask() {
    int bl = blockIdx.x, w = blockIdx.y;
    int nv = g_nv[bl];
    int j0 = w << 6;
    if (j0 >= nv) return;
    __shared__ float4 jb[64];
    __shared__ float  ja[64];
    int tid = threadIdx.x;
    int jend = min(j0 + 64, nv);
    if (tid < jend - j0) { jb[tid] = g_obox[bl][j0 + tid]; ja[tid] = g_oar[bl][j0 + tid]; }
    __syncthreads();
    for (int i = tid; i < nv; i += 256) {
        u64 mword = 0;
        int js = max(j0, i + 1) - j0, je = jend - j0;
        if (js < je) {
            float4 bi = g_obox[bl][i];
            float ai = g_oar[bl][i];
            for (int jj = js; jj < je; jj++) {
                float4 bj = jb[jj];
                float lx = fmaxf(bi.x, bj.x), ly = fmaxf(bi.y, bj.y);
                float rx = fminf(bi.z, bj.z), ry = fminf(bi.w, bj.w);
                float ww2 = rx - lx, hh2 = ry - ly;
                if (ww2 > 0.0f && hh2 > 0.0f) {
                    float inter = ww2 * hh2;
                    float uni = ai + ja[jj] - inter + 1e-9f;
                    if (__fdiv_rn(inter, uni) > 0.7f) mword |= 1ULL << jj;
                }
            }
        }
        g_mask[bl][i][w] = mword;
    }
}

// ---- K4: fixed-point greedy NMS + compact --------------------------------
#define SMEM5 (131072 + 512)
__global__ __launch_bounds__(1024, 1)
void k_nms() {
    extern __shared__ unsigned char sm[];
    u64* smask = (u64*)sm;
    u64* cur   = (u64*)(sm + 131072);
    u64* nxt   = cur + 16;
    int* misc  = (int*)(nxt + 16);
    int tid = threadIdx.x, bl = blockIdx.x;
    int nv = g_nv[bl];
    const u64* gm = &g_mask[bl][0][0];
    for (int t = tid; t < nv * 16; t += 1024) smask[t] = gm[t];
    if (tid < 16) cur[tid] = 0ULL;
    __syncthreads();

    int w = tid & 15, i0 = tid >> 4;
    for (int it = 0; it < NPAD; it++) {
        if (tid < 16) nxt[tid] = 0ULL;
        if (tid == 0) misc[0] = 0;
        __syncthreads();
        u64 acc = 0;
        for (int i = i0; i < nv; i += 64)
            if (!((cur[i >> 6] >> (i & 63)) & 1ULL)) acc |= smask[i * 16 + w];
        if (acc) atomicOr(&nxt[w], acc);
        __syncthreads();
        if (tid < 16) {
            if (nxt[tid] != cur[tid]) misc[0] = 1;
            cur[tid] = nxt[tid];
        }
        __syncthreads();
        if (!misc[0]) break;
    }

    int keepf = (tid < nv) && !((cur[tid >> 6] >> (tid & 63)) & 1ULL);
    int ktot;
    int kpos = bscan(keepf, misc + 4, tid, &ktot);
    if (keepf) {
        g_kb[bl][kpos] = g_ubox[bl][tid];
        g_kkey[bl][kpos] = g_sig[bl][tid];
    }
    if (tid == 0) g_kcnt[bl] = ktot;
}

// ---- K5: sortless merge, one block per (b,l) -----------------------------
// rank(l,p,s) = p + sum_{l'<l} #{key' >= s} + sum_{l'>l} #{key' > s}
__global__ __launch_bounds__(1024, 1)
void k_merge(float* __restrict__ out) {
    __shared__ u32 skeys[NLVL][NPAD];
    __shared__ int cnt[NLVL], off[NLVL + 1];
    int bl = blockIdx.x, b = bl / NLVL, l = bl % NLVL;
    int tid = threadIdx.x;
    if (tid < NLVL) cnt[tid] = g_kcnt[b * NLVL + tid];
    __syncthreads();
    if (tid == 0) {
        int s = 0;
        for (int q = 0; q < NLVL; q++) { off[q] = s; s += cnt[q]; }
        off[NLVL] = s;
    }
    __syncthreads();
    int total = off[NLVL];
    for (int l2 = 0; l2 < NLVL; l2++)
        for (int p = tid; p < cnt[l2]; p += 1024)
            skeys[l2][p] = g_kkey[b * NLVL + l2][p];
    __syncthreads();

    if (l == 0)
        for (int j = total + tid; j < 1000; j += 1024)
            ((float4*)out)[b * 1000 + j] = make_float4(0.f, 0.f, 0.f, 0.f);

    int p = tid;
    if (p < cnt[l]) {
        u32 s = skeys[l][p];
        int rank = p;
#pragma unroll
        for (int l2 = 0; l2 < NLVL; l2++) {
            if (l2 == l) continue;
            const u32* a = skeys[l2];
            int lo = 0, hi = cnt[l2];
            if (l2 < l) {
                while (lo < hi) { int mid = (lo + hi) >> 1; if (a[mid] < s) hi = mid; else lo = mid + 1; }
            } else {
                while (lo < hi) { int mid = (lo + hi) >> 1; if (a[mid] <= s) hi = mid; else lo = mid + 1; }
            }
            rank += lo;
        }
        if (rank < 1000)
            ((float4*)out)[b * 1000 + rank] = g_kb[b * NLVL + l][p];
    }
}

static bool msz(const int* s, const int* ref) {
    for (int i = 0; i < 11; i++) if (s[i] != ref[i]) return false;
    return true;
}

extern "C" void kernel_launch(void* const* d_in, const int* in_sizes, int n_in,
                              void* d_out, int out_size) {
    const float *o[5], *dl[5], *anch;
    static const int inter[11] = {960000, 3840000, 240000, 960000, 60000,
                                  240000, 15000, 60000, 4056, 16224, 639528};
    static const int alpha[11] = {639528, 3840000, 960000, 240000, 60000,
                                  16224, 960000, 240000, 60000, 15000, 4056};
    if (n_in >= 11 && msz(in_sizes, inter)) {
        for (int i = 0; i < 5; i++) { o[i] = (const float*)d_in[2 * i]; dl[i] = (const float*)d_in[2 * i + 1]; }
        anch = (const float*)d_in[10];
    } else if (n_in >= 11 && msz(in_sizes, alpha)) {
        anch = (const float*)d_in[0];
        for (int i = 0; i < 5; i++) { dl[i] = (const float*)d_in[1 + i]; o[i] = (const float*)d_in[6 + i]; }
    } else {
        for (int i = 0; i < 5; i++) { o[i] = (const float*)d_in[i]; dl[i] = (const float*)d_in[5 + i]; }
        anch = (const float*)d_in[10];
    }
    (void)out_size;

    static int attr_done = 0;
    if (!attr_done) {
        cudaFuncSetAttribute(k_sortdecode, cudaFuncAttributeMaxDynamicSharedMemorySize, SMEM3);
        cudaFuncSetAttribute(k_nms, cudaFuncAttributeMaxDynamicSharedMemorySize, SMEM5);
        attr_done = 1;
    }

    k_histthresh<<<dim3(NBL, NCH), 256>>>(o[0], o[1], o[2], o[3]);
    k_compact<<<dim3(NBL, NCH), 256>>>(o[0], o[1], o[2], o[3]);
    k_sortdecode<<<NBL, 1024, SMEM3>>>(o[4], dl[0], dl[1], dl[2], dl[3], dl[4], anch);
    k_mask<<<dim3(NBL, 16), 256>>>();
    k_nms<<<NBL, 1024, SMEM5>>>();
    k_merge<<<NBL, 1024>>>((float*)d_out);
}

// round 10
// speedup vs baseline: 3.0681x; 1.0143x over previous
#include <cuda_runtime.h>
#include <cstdint>

typedef unsigned long long u64;
typedef unsigned int u32;

#define NBATCH 8
#define NLVL 5
#define NBL 40
#define NCH 16
#define NPAD 1024
#define CAND 4096
#define IMGSZ 800.0f
#define CLIPV 4.135166556742356f

__constant__ int c_h[NLVL]   = {200, 100, 50, 25, 13};
__constant__ int c_n[NLVL]   = {120000, 30000, 7500, 1875, 507};
__constant__ int c_off[NLVL] = {0, 120000, 150000, 157500, 159375};
__constant__ int c_k[NLVL]   = {1000, 1000, 1000, 1000, 507};
__constant__ int c_nch[NLVL] = {16, 4, 1, 1, 0};   // hist chunks per level

__device__ u32    g_hist16[NBL][NCH][4096];
__device__ u32    g_B[NBL];
__device__ int    g_ccnt[NBL];
__device__ int    g_arrive[NBL];      // zero-init; reset by consumer
__device__ u64    g_cand[NBL][CAND];
__device__ float4 g_obox[NBL][NPAD];
__device__ float  g_oar [NBL][NPAD];
__device__ float4 g_ubox[NBL][NPAD];
__device__ u32    g_sig [NBL][NPAD];
__device__ int    g_nv  [NBL];
__device__ u64    g_mask[NBL][NPAD][16];
__device__ float4 g_kb  [NBL][NPAD];
__device__ u32    g_kkey[NBL][NPAD];
__device__ int    g_kcnt[NBL];

__device__ __forceinline__ u32 fkey(float f) {
    u32 u = __float_as_uint(f);
    return u ^ ((u32)((int)u >> 31) | 0x80000000u);
}
__device__ __forceinline__ float unfkey(u32 enc) {
    u32 u = (enc & 0x80000000u) ? (enc ^ 0x80000000u) : ~enc;
    return __uint_as_float(u);
}

__device__ __forceinline__ int bscan(int v, int* ws, int tid, int* total) {
    int lane = tid & 31, wid = tid >> 5;
    int x = v;
#pragma unroll
    for (int o = 1; o < 32; o <<= 1) {
        int y = __shfl_up_sync(~0u, x, o);
        if (lane >= o) x += y;
    }
    if (lane == 31) ws[wid] = x;
    __syncthreads();
    if (wid == 0) {
        int y = ws[lane];
#pragma unroll
        for (int o = 1; o < 32; o <<= 1) {
            int z = __shfl_up_sync(~0u, y, o);
            if (lane >= o) y += z;
        }
        ws[lane] = y;
    }
    __syncthreads();
    int base = wid ? ws[wid - 1] : 0;
    int tot = ws[31];
    __syncthreads();
    *total = tot;
    return base + x - v;
}

// Hybrid-barrier bitonic sort, descending (bit-identical comparator).
__device__ __forceinline__ void bitonic_desc(u64* a, int n, int tid) {
    bool prev_big = true;
    for (int sz = 2; sz <= n; sz <<= 1)
        for (int st = sz >> 1; st >= 1; st >>= 1) {
            bool big = (st >= 64);
            if (big || prev_big) __syncthreads(); else __syncwarp();
            prev_big = big;
            for (int t = tid; t < (n >> 1); t += 1024) {
                int i = t + (t & ~(st - 1));
                int j = i + st;
                u64 x = a[i], y = a[j];
                if (((i & sz) == 0) ? (x < y) : (x > y)) { a[i] = y; a[j] = x; }
            }
        }
    __syncthreads();
}

// ---- K0: chunk histograms; last-arriving chunk block picks threshold ------
__global__ void k_histthresh(const float* __restrict__ o0, const float* __restrict__ o1,
                             const float* __restrict__ o2, const float* __restrict__ o3) {
    int bl = blockIdx.x, c = blockIdx.y, tid = threadIdx.x;
    int b = bl / NLVL, l = bl % NLVL;
    if (l == 4) return;
    int nch = c_nch[l];
    if (c >= nch) return;
    int h2 = c_h[l] * c_h[l], n = c_n[l];
    const float* ob = ((l == 0) ? o0 : (l == 1) ? o1 : (l == 2) ? o2 : o3) + (size_t)b * 3 * h2;
    __shared__ u32 hist[4096];
    __shared__ int misc[160];
    __shared__ int lastf;
    for (int q = tid; q < 4096; q += 256) hist[q] = 0;
    __syncthreads();
    if (l < 3) {
        const float4* ob4 = (const float4*)ob;
        int n4 = n >> 2, cs = (n4 + nch - 1) / nch;
        int qs = c * cs, qe = min(qs + cs, n4);
        for (int q = qs + tid; q < qe; q += 256) {
            float4 v = ob4[q];
            atomicAdd(&hist[fkey(v.x) >> 20], 1u);
            atomicAdd(&hist[fkey(v.y) >> 20], 1u);
            atomicAdd(&hist[fkey(v.z) >> 20], 1u);
            atomicAdd(&hist[fkey(v.w) >> 20], 1u);
        }
    } else {
        for (int q = tid; q < n; q += 256)
            atomicAdd(&hist[fkey(ob[q]) >> 20], 1u);
    }
    __syncthreads();
    for (int q = tid; q < 4096; q += 256) g_hist16[bl][c][q] = hist[q];
    __threadfence();
    if (tid == 0) lastf = (atomicAdd(&g_arrive[bl], 1) == nch - 1);
    __syncthreads();
    if (!lastf) return;
    __threadfence();
    for (int j = tid; j < 4096; j += 256) {
        u32 s = 0;
        for (int c2 = 0; c2 < nch; c2++) s += g_hist16[bl][c2][j];
        hist[j] = s;
    }
    __syncthreads();
    if (tid < 128) {
        u32 s = 0;
        for (int q = 0; q < 32; q++) s += hist[tid * 32 + q];
        misc[tid + 8] = (int)s;
    }
    __syncthreads();
    if (tid == 0) {
        int kk = c_k[l];
        int acc = 0, cc;
        for (cc = 127; cc > 0; cc--) {
            if (acc + misc[cc + 8] >= kk) break;
            acc += misc[cc + 8];
        }
        int bsel = cc * 32;
        for (int q = 31; q >= 0; q--) {
            int hv = (int)hist[cc * 32 + q];
            if (acc + hv >= kk) { bsel = cc * 32 + q; break; }
            acc += hv;
        }
        g_B[bl] = (u32)bsel;
        g_ccnt[bl] = 0;
        g_arrive[bl] = 0;   // ready for next replay
    }
}

// ---- K1: compact candidates >= threshold bucket ---------------------------
__global__ void k_compact(const float* __restrict__ o0, const float* __restrict__ o1,
                          const float* __restrict__ o2, const float* __restrict__ o3) {
    int bl = blockIdx.x, c = blockIdx.y, tid = threadIdx.x;
    int b = bl / NLVL, l = bl % NLVL;
    if (l == 4) return;
    int h2 = c_h[l] * c_h[l], n = c_n[l];
    const float* ob = ((l == 0) ? o0 : (l == 1) ? o1 : (l == 2) ? o2 : o3) + (size_t)b * 3 * h2;
    u32 B = g_B[bl];
    if (l < 3) {
        const float4* ob4 = (const float4*)ob;
        int n4 = n >> 2, cs = (n4 + NCH - 1) / NCH;
        int qs = c * cs, qe = min(qs + cs, n4);
        for (int q = qs + tid; q < qe; q += 256) {
            float4 v = ob4[q];
            float vv[4] = {v.x, v.y, v.z, v.w};
#pragma unroll
            for (int e4 = 0; e4 < 4; e4++) {
                u32 u = fkey(vv[e4]);
                if ((u >> 20) >= B) {
                    int pos = atomicAdd(&g_ccnt[bl], 1);
                    if (pos < CAND) {
                        int i0 = 4 * q + e4;
                        int a = (i0 >= h2) + (i0 >= 2 * h2);
                        int p = i0 - a * h2;
                        g_cand[bl][pos] = ((u64)u << 32) | (u32)(~(u32)(p * 3 + a));
                    }
                }
            }
        }
    } else {
        int cs = (n + NCH - 1) / NCH;
        int qs = c * cs, qe = min(qs + cs, n);
        for (int q = qs + tid; q < qe; q += 256) {
            u32 u = fkey(ob[q]);
            if ((u >> 20) >= B) {
                int pos = atomicAdd(&g_ccnt[bl], 1);
                if (pos < CAND) {
                    int a = (q >= h2) + (q >= 2 * h2);
                    int p = q - a * h2;
                    g_cand[bl][pos] = ((u64)u << 32) | (u32)(~(u32)(p * 3 + a));
                }
            }
        }
    }
}

// ---- K2: per (b,l): sort candidates -> decode -> validity compact ---------
#define SMEM3 (CAND * 8 + 1024)
__global__ __launch_bounds__(1024, 1)
void k_sortdecode(const float* __restrict__ o4,
                  const float* __restrict__ dl0, const float* __restrict__ dl1,
                  const float* __restrict__ dl2, const float* __restrict__ dl3,
                  const float* __restrict__ dl4, const float* __restrict__ anchors) {
    extern __shared__ unsigned char sm[];
    u64* cand = (u64*)sm;
    int* misc = (int*)(sm + CAND * 8);
    int tid = threadIdx.x;
    int bl = blockIdx.x, b = bl / NLVL, l = bl % NLVL;
    int h = c_h[l], n = c_n[l], kk = c_k[l], h2 = h * h;

    int S;
    if (l == 4) {
        const float* ob = o4 + (size_t)b * 3 * h2;
        for (int j = tid; j < NPAD; j += 1024) {
            u64 e = 0ULL;
            if (j < n) {
                int p = j / 3, a = j - p * 3, y = p / h, x = p - y * h;
                float v = ob[(a * h + y) * h + x];
                e = ((u64)fkey(v) << 32) | (u32)(~(u32)j);
            }
            cand[j] = e;
        }
        S = 1024;
    } else {
        int m = g_ccnt[bl];
        if (m > CAND) m = CAND;
        S = (m <= 1024) ? 1024 : ((m <= 2048) ? 2048 : 4096);
        for (int q = tid; q < S; q += 1024)
            cand[q] = (q < m) ? g_cand[bl][q] : 0ULL;
    }

    bitonic_desc(cand, S, tid);   // (key desc, idx asc) == lax.top_k order

    float C = 4096.0f * (float)l;
    const float* dl = (l == 0) ? dl0 : (l == 1) ? dl1 : (l == 2) ? dl2 : (l == 3) ? dl3 : dl4;
    int valid = 0;
    float cx1 = 0.f, cy1 = 0.f, cx2 = 0.f, cy2 = 0.f;
    u32 sigbits = 0;
    if (tid < kk) {
        u64 e = cand[tid];
        u32 idx = ~(u32)(e & 0xFFFFFFFFu);
        float logit = unfkey((u32)(e >> 32));
        sigbits = __float_as_uint(__fdiv_rn(1.0f, 1.0f + expf(-logit)));
        int p = (int)(idx / 3u), a = (int)idx - p * 3;
        int y = p / h, x = p - y * h;
        int gi = c_off[l] + (int)idx;
        float ax1 = anchors[4 * gi], ay1 = anchors[4 * gi + 1];
        float ax2 = anchors[4 * gi + 2], ay2 = anchors[4 * gi + 3];
        float wa = ax2 - ax1, ha = ay2 - ay1;
        float cxa = ax1 + 0.5f * wa, cya = ay1 + 0.5f * ha;
        int dbase = ((b * 12 + a * 4) * h + y) * h + x;
        float dx = dl[dbase], dy = dl[dbase + h2];
        float dw = fminf(dl[dbase + 2 * h2], CLIPV);
        float dh = fminf(dl[dbase + 3 * h2], CLIPV);
        float cx = dx * wa + cxa, cy = dy * ha + cya;
        float pw = expf(dw) * wa, ph = expf(dh) * ha;
        cx1 = fminf(fmaxf(cx - 0.5f * pw, 0.0f), IMGSZ);
        cy1 = fminf(fmaxf(cy - 0.5f * ph, 0.0f), IMGSZ);
        cx2 = fminf(fmaxf(cx + 0.5f * pw, 0.0f), IMGSZ);
        cy2 = fminf(fmaxf(cy + 0.5f * ph, 0.0f), IMGSZ);
        valid = ((cx2 - cx1) >= 1e-3f && (cy2 - cy1) >= 1e-3f) ? 1 : 0;
    }
    __syncthreads();

    int nv;
    int vpos = bscan(valid, misc, tid, &nv);
    if (valid) {
        float xo1 = cx1 + C, yo1 = cy1 + C, xo2 = cx2 + C, yo2 = cy2 + C;
        g_obox[bl][vpos] = make_float4(xo1, yo1, xo2, yo2);
        g_oar[bl][vpos] = (xo2 - xo1) * (yo2 - yo1);
        g_ubox[bl][vpos] = make_float4(cx1, cy1, cx2, cy2);
        g_sig[bl][vpos] = sigbits;
    }
    if (tid == 0) g_nv[bl] = nv;
}

// ---- K3: mask builder, grid (40, 16, 4) x 256: one row per thread --------
__global__ void k_mask() {
    int bl = blockIdx.x, w = blockIdx.y, z = blockIdx.z;
    int nv = g_nv[bl];
    int j0 = w << 6;
    if (j0 >= nv) return;               // stale words harmless (bits >= nv only)
    int i = (z << 8) + threadIdx.x;     // one row per thread
    if ((z << 8) >= nv) return;
    __shared__ float4 jb[64];
    __shared__ float  ja[64];
    int tid = threadIdx.x;
    int jend = min(j0 + 64, nv);
    if (tid < jend - j0) { jb[tid] = g_obox[bl][j0 + tid]; ja[tid] = g_oar[bl][j0 + tid]; }
    __syncthreads();
    if (i >= nv) return;
    u64 mword = 0;
    int js = max(j0, i + 1) - j0, je = jend - j0;
    if (js < je) {
        float4 bi = g_obox[bl][i];
        float ai = g_oar[bl][i];
        for (int jj = js; jj < je; jj++) {
            float4 bj = jb[jj];
            float lx = fmaxf(bi.x, bj.x), ly = fmaxf(bi.y, bj.y);
            float rx = fminf(bi.z, bj.z), ry = fminf(bi.w, bj.w);
            float ww2 = rx - lx, hh2 = ry - ly;
            if (ww2 > 0.0f && hh2 > 0.0f) {
                float inter = ww2 * hh2;
                float uni = ai + ja[jj] - inter + 1e-9f;
                if (__fdiv_rn(inter, uni) > 0.7f) mword |= 1ULL << jj;
            }
        }
    }
    g_mask[bl][i][w] = mword;
}

// ---- K4: fixed-point greedy NMS + compact --------------------------------
#define SMEM5 (131072 + 512)
__global__ __launch_bounds__(1024, 1)
void k_nms() {
    extern __shared__ unsigned char sm[];
    u64* smask = (u64*)sm;
    u64* cur   = (u64*)(sm + 131072);
    u64* nxt   = cur + 16;
    int* misc  = (int*)(nxt + 16);
    int tid = threadIdx.x, bl = blockIdx.x;
    int nv = g_nv[bl];
    const u64* gm = &g_mask[bl][0][0];
    for (int t = tid; t < nv * 16; t += 1024) smask[t] = gm[t];
    if (tid < 16) cur[tid] = 0ULL;
    __syncthreads();

    int w = tid & 15, i0 = tid >> 4;
    for (int it = 0; it < NPAD; it++) {
        if (tid < 16) nxt[tid] = 0ULL;
        if (tid == 0) misc[0] = 0;
        __syncthreads();
        u64 acc = 0;
        for (int i = i0; i < nv; i += 64)
            if (!((cur[i >> 6] >> (i & 63)) & 1ULL)) acc |= smask[i * 16 + w];
        if (acc) atomicOr(&nxt[w], acc);
        __syncthreads();
        if (tid < 16) {
            if (nxt[tid] != cur[tid]) misc[0] = 1;
            cur[tid] = nxt[tid];
        }
        __syncthreads();
        if (!misc[0]) break;
    }

    int keepf = (tid < nv) && !((cur[tid >> 6] >> (tid & 63)) & 1ULL);
    int ktot;
    int kpos = bscan(keepf, misc + 4, tid, &ktot);
    if (keepf) {
        g_kb[bl][kpos] = g_ubox[bl][tid];
        g_kkey[bl][kpos] = g_sig[bl][tid];
    }
    if (tid == 0) g_kcnt[bl] = ktot;
}

// ---- K5: sortless merge, one block per (b,l) -----------------------------
__global__ __launch_bounds__(1024, 1)
void k_merge(float* __restrict__ out) {
    __shared__ u32 skeys[NLVL][NPAD];
    __shared__ int cnt[NLVL], off[NLVL + 1];
    int bl = blockIdx.x, b = bl / NLVL, l = bl % NLVL;
    int tid = threadIdx.x;
    if (tid < NLVL) cnt[tid] = g_kcnt[b * NLVL + tid];
    __syncthreads();
    if (tid == 0) {
        int s = 0;
        for (int q = 0; q < NLVL; q++) { off[q] = s; s += cnt[q]; }
        off[NLVL] = s;
    }
    __syncthreads();
    int total = off[NLVL];
    for (int l2 = 0; l2 < NLVL; l2++)
        for (int p = tid; p < cnt[l2]; p += 1024)
            skeys[l2][p] = g_kkey[b * NLVL + l2][p];
    __syncthreads();

    if (l == 0)
        for (int j = total + tid; j < 1000; j += 1024)
            ((float4*)out)[b * 1000 + j] = make_float4(0.f, 0.f, 0.f, 0.f);

    int p = tid;
    if (p < cnt[l]) {
        u32 s = skeys[l][p];
        int rank = p;
#pragma unroll
        for (int l2 = 0; l2 < NLVL; l2++) {
            if (l2 == l) continue;
            const u32* a = skeys[l2];
            int lo = 0, hi = cnt[l2];
            if (l2 < l) {
                while (lo < hi) { int mid = (lo + hi) >> 1; if (a[mid] < s) hi = mid; else lo = mid + 1; }
            } else {
                while (lo < hi) { int mid = (lo + hi) >> 1; if (a[mid] <= s) hi = mid; else lo = mid + 1; }
            }
            rank += lo;
        }
        if (rank < 1000)
            ((float4*)out)[b * 1000 + rank] = g_kb[b * NLVL + l][p];
    }
}

static bool msz(const int* s, const int* ref) {
    for (int i = 0; i < 11; i++) if (s[i] != ref[i]) return false;
    return true;
}

extern "C" void kernel_launch(void* const* d_in, const int* in_sizes, int n_in,
                              void* d_out, int out_size) {
    const float *o[5], *dl[5], *anch;
    static const int inter[11] = {960000, 3840000, 240000, 960000, 60000,
                                  240000, 15000, 60000, 4056, 16224, 639528};
    static const int alpha[11] = {639528, 3840000, 960000, 240000, 60000,
                                  16224, 960000, 240000, 60000, 15000, 4056};
    if (n_in >= 11 && msz(in_sizes, inter)) {
        for (int i = 0; i < 5; i++) { o[i] = (const float*)d_in[2 * i]; dl[i] = (const float*)d_in[2 * i + 1]; }
        anch = (const float*)d_in[10];
    } else if (n_in >= 11 && msz(in_sizes, alpha)) {
        anch = (const float*)d_in[0];
        for (int i = 0; i < 5; i++) { dl[i] = (const float*)d_in[1 + i]; o[i] = (const float*)d_in[6 + i]; }
    } else {
        for (int i = 0; i < 5; i++) { o[i] = (const float*)d_in[i]; dl[i] = (const float*)d_in[5 + i]; }
        anch = (const float*)d_in[10];
    }
    (void)out_size;

    static int attr_done = 0;
    if (!attr_done) {
        cudaFuncSetAttribute(k_sortdecode, cudaFuncAttributeMaxDynamicSharedMemorySize, SMEM3);
        cudaFuncSetAttribute(k_nms, cudaFuncAttributeMaxDynamicSharedMemorySize, SMEM5);
        attr_done = 1;
    }

    k_histthresh<<<dim3(NBL, NCH), 256>>>(o[0], o[1], o[2], o[3]);
    k_compact<<<dim3(NBL, NCH), 256>>>(o[0], o[1], o[2], o[3]);
    k_sortdecode<<<NBL, 1024, SMEM3>>>(o[4], dl[0], dl[1], dl[2], dl[3], dl[4], anch);
    k_mask<<<dim3(NBL, 16, 4), 256>>>();
    k_nms<<<NBL, 1024, SMEM5>>>();
    k_merge<<<NBL, 1024>>>((float*)d_out);
}